// round 14
// baseline (speedup 1.0000x reference)
#include <cuda_runtime.h>
#include <cstdint>

constexpr int T = 512, B = 64, F = 32, K = 32;

#define FULL 0xffffffffu
#define VOLI(x) (*(volatile int*)&(x))

__device__ __forceinline__ float ex2f(float x) {
    float y; asm("ex2.approx.f32 %0, %1;" : "=f"(y) : "f"(x)); return y;
}
__device__ __forceinline__ float lg2f(float x) {
    float y; asm("lg2.approx.f32 %0, %1;" : "=f"(y) : "f"(x)); return y;
}

constexpr float L2E  = 1.4426950408889634f;
constexpr float LN2  = 0.6931471805599453f;
constexpr float LN32 = 3.4657359027997265f;

constexpr int FR = 256;            // feats ring rows (32 KB)

// One block per batch b, 4 warps:
//   wid 0,1 : feats producers (rows t≡wid mod 2) -> global feats + smem ring;
//             then backpointer consumers trailing vit via s_vw (R7 logic).
//   wid 2   : forward chain (linear domain) -> score[b]
//   wid 3   : Viterbi chain -> maxs[1..], watermark s_vw
__global__ void __launch_bounds__(128, 1)
crf_all(const int* __restrict__ words, const int* __restrict__ lens,
        const float* __restrict__ W, const float* __restrict__ trans,
        float* __restrict__ feats, float* __restrict__ maxs,
        float* __restrict__ idxo, float* __restrict__ score)
{
    __shared__ float ring[FR][K];
    __shared__ int s_fw[2];        // producer p: rows of parity p, <= s_fw[p], done
    __shared__ int s_cons[2];      // fwd/vit consumed-up-to (ring backpressure)
    __shared__ int s_vw;           // maxs[<=s_vw] visible

    int tid  = threadIdx.x;
    int wid  = tid >> 5;
    int lane = tid & 31;
    int b    = blockIdx.x;

    if (tid < 2) { s_fw[tid] = -1; s_cons[tid] = 0; }
    if (tid == 0) s_vw = 0;
    __syncthreads();

    int L = __ldg(&lens[b]);       // uniform within block

    if (wid < 2) {
        // ==================== producer phase ====================
        int p = wid;
        float w0v = __ldg(&W[0]) * 32.f;      // pad row: idx->0 after tag shift
        // software pipeline: preload words for the first owned row
        int wcur = (p < L) ? __ldg(&words[(p * B + b) * F + lane]) : 0;

        for (int t = p; t < T; t += 2) {
            int tn = t + 2;
            int wnext = (tn < L) ? __ldg(&words[(tn * B + b) * F + lane]) : 0;

            if (t >= FR - 8) {     // ring backpressure
                while (min(VOLI(s_cons[0]), VOLI(s_cons[1])) < t - (FR - 8))
                    __nanosleep(64);
            }
            float s;
            if (t < L) {
                float s0 = 0.f, s1 = 0.f, s2 = 0.f, s3 = 0.f;
#pragma unroll
                for (int f = 0; f < F; f += 4) {
                    int w0 = __shfl_sync(FULL, wcur, f);
                    int w1 = __shfl_sync(FULL, wcur, f + 1);
                    int w2 = __shfl_sync(FULL, wcur, f + 2);
                    int w3 = __shfl_sync(FULL, wcur, f + 3);
                    s0 += __ldg(&W[w0 + lane]); s1 += __ldg(&W[w1 + lane]);
                    s2 += __ldg(&W[w2 + lane]); s3 += __ldg(&W[w3 + lane]);
                }
                s = (s0 + s1) + (s2 + s3);
            } else {
                s = w0v;
            }
            feats[(t * B + b) * K + lane] = s;
            if (t == 0) {
                maxs[b * K + lane] = s;        // max_s[0] = feats[0]
                idxo[b * K + lane] = 0.f;      // max_s_idx[0] = 0
            }
            ring[t & (FR - 1)][lane] = s;
            __syncwarp();
            __threadfence_block();
            __syncwarp();
            if (lane == 0) VOLI(s_fw[p]) = t;
            wcur = wnext;
        }
        __syncwarp();
        if (lane == 0) VOLI(s_fw[p]) = T;      // final release

        // both producers done => all feats/maxs[0]/idxo[0] writes visible
        while (min(VOLI(s_fw[0]), VOLI(s_fw[1])) < T) __nanosleep(32);
        __threadfence_block();

        // ==================== bp phase (R7 logic) ====================
        float tc[K];
#pragma unroll
        for (int j = 0; j < K; j++) tc[j] = __ldg(&trans[j * K + lane]);

        int q = p;
        int Lc = (L < T) ? L : T;
        for (int t = 1 + q; t < Lc; t += 2) {
            while (VOLI(s_vw) < t - 1) __nanosleep(32);
            __threadfence_block();
            float dp = maxs[((t - 1) * B + b) * K + lane];

            float best = __shfl_sync(FULL, dp, 0) + tc[0];
            int   bi   = 0;
#pragma unroll
            for (int j = 1; j < K; j++) {
                float sc = __shfl_sync(FULL, dp, j) + tc[j];
                if (sc > best) { best = sc; bi = j; }   // strict > : first index
            }
            idxo[(t * B + b) * K + lane] = (float)bi;
        }
        if (L < T) {
            while (VOLI(s_vw) < L - 1) __nanosleep(32);
            __threadfence_block();
            float dp = maxs[((L - 1) * B + b) * K + lane];

            float best = __shfl_sync(FULL, dp, 0) + tc[0];
            int   bi   = 0;
#pragma unroll
            for (int j = 1; j < K; j++) {
                float sc = __shfl_sync(FULL, dp, j) + tc[j];
                if (sc > best) { best = sc; bi = j; }
            }
            float v = (float)bi;
            int t0 = L + (((1 + q) - L) & 1);           // first t>=L, right parity
            if (t0 < 1 + q) t0 = 1 + q;
#pragma unroll 4
            for (int t = t0; t < T; t += 2)
                idxo[(t * B + b) * K + lane] = v;
        }
        return;
    }

    // ==================== chain warps ====================
    auto wait_fw = [&](int need) {
        while (min(VOLI(s_fw[0]), VOLI(s_fw[1])) < need) { }
        __threadfence_block();
    };

    if (wid == 2) {
        // ---------------- forward chain (linear domain) ----------------
        float et[K];
#pragma unroll
        for (int j = 0; j < K; j++) et[j] = ex2f(__ldg(&trans[j * K + lane]) * L2E);

        wait_fw(min(16, T - 1));
        float f0 = ring[0][lane];
        float C0 = __shfl_sync(FULL, f0, 0);
        float E    = ex2f((f0 - C0) * L2E);
        float Ctot = C0;

        for (int base = 1; base < L; base += 16) {
            wait_fw(min(base + 15, T - 1));
            if (lane == 0) VOLI(s_cons[0]) = base - 1;
            int end = min(base + 16, L);
            for (int t = base; t < end; t++) {
                float f  = ring[t & (FR - 1)][lane];
                float xf = ex2f(fmaf(f, L2E, -5.f));    // exp(f)/32, off-path

                float s0 = 0.f, s1 = 0.f, s2 = 0.f, s3 = 0.f;
#pragma unroll
                for (int j = 0; j < K; j += 4) {
                    s0 = fmaf(__shfl_sync(FULL, E, j),     et[j],     s0);
                    s1 = fmaf(__shfl_sync(FULL, E, j + 1), et[j + 1], s1);
                    s2 = fmaf(__shfl_sync(FULL, E, j + 2), et[j + 2], s2);
                    s3 = fmaf(__shfl_sync(FULL, E, j + 3), et[j + 3], s3);
                }
                E = ((s0 + s1) + (s2 + s3)) * xf;
                Ctot += LN32;
                if ((t & 127) == 0) {                   // renorm (alpha-preserving)
                    float rr = __shfl_sync(FULL, E, 0);
                    float cc = lg2f(rr);
                    E *= ex2f(-cc);
                    Ctot += cc * LN2;
                }
            }
        }
        float e = E;
#pragma unroll
        for (int o = 16; o; o >>= 1) e += __shfl_xor_sync(FULL, e, o);
        if (lane == 0) score[b] = Ctot + lg2f(e) * LN2;
        __syncwarp();
        if (lane == 0) VOLI(s_cons[0]) = T + FR;        // release producers

    } else {
        // ---------------- Viterbi chain ----------------
        float tc[K];
#pragma unroll
        for (int j = 0; j < K; j++) tc[j] = __ldg(&trans[j * K + lane]);

        wait_fw(min(16, T - 1));
        float delta = ring[0][lane];

        const float NEG_INF = __int_as_float(0xff800000);
        for (int base = 1; base < L; base += 16) {
            wait_fw(min(base + 15, T - 1));
            __syncwarp();
            __threadfence_block();
            if (lane == 0) { VOLI(s_vw) = base - 1; VOLI(s_cons[1]) = base - 1; }
            __syncwarp();
            int end = min(base + 16, L);
            for (int t = base; t < end; t++) {
                float f = ring[t & (FR - 1)][lane];

                float m0 = NEG_INF, m1 = NEG_INF, m2 = NEG_INF, m3 = NEG_INF;
#pragma unroll
                for (int j = 0; j < K; j += 4) {
                    m0 = fmaxf(m0, __shfl_sync(FULL, delta, j)     + tc[j]);
                    m1 = fmaxf(m1, __shfl_sync(FULL, delta, j + 1) + tc[j + 1]);
                    m2 = fmaxf(m2, __shfl_sync(FULL, delta, j + 2) + tc[j + 2]);
                    m3 = fmaxf(m3, __shfl_sync(FULL, delta, j + 3) + tc[j + 3]);
                }
                delta = fmaxf(fmaxf(m0, m1), fmaxf(m2, m3)) + f;
                maxs[(t * B + b) * K + lane] = delta;
            }
        }
        // unblock bp up to L-1, then frozen tail
        __syncwarp();
        __threadfence_block();
        if (lane == 0) VOLI(s_vw) = L - 1;
        __syncwarp();
#pragma unroll 4
        for (int t = L; t < T; t++)
            maxs[(t * B + b) * K + lane] = delta;
        __syncwarp();
        __threadfence_block();
        if (lane == 0) { VOLI(s_vw) = T; VOLI(s_cons[1]) = T + FR; }
    }
}

// ---------------------------------------------------------------------------
extern "C" void kernel_launch(void* const* d_in, const int* in_sizes, int n_in,
                              void* d_out, int out_size) {
    const int*   words = (const int*)d_in[0];     // [T,B,F] int32
    const int*   lens  = (const int*)d_in[1];     // [B] int32
    const float* W     = (const float*)d_in[2];   // [1e6] f32
    const float* trans = (const float*)d_in[3];   // [K,K] f32
    float* out   = (float*)d_out;
    float* score = out;
    float* maxs  = out + 64;
    float* idxo  = out + 64 + T * B * K;
    float* feats = out + 64 + 2 * T * B * K;

    crf_all<<<B, 128>>>(words, lens, W, trans, feats, maxs, idxo, score);
}

// round 15
// speedup vs baseline: 2.2861x; 2.2861x over previous
#include <cuda_runtime.h>
#include <cstdint>

constexpr int T = 512, B = 64, F = 32, K = 32;

#define FULL 0xffffffffu

__device__ int g_fw[B];   // feats watermark: rows <= g_fw[b] visible (gpu scope)
__device__ int g_vw[B];   // viterbi watermark: maxs[<=g_vw[b]] visible

__device__ __forceinline__ float ex2f(float x) {
    float y; asm("ex2.approx.f32 %0, %1;" : "=f"(y) : "f"(x)); return y;
}
__device__ __forceinline__ float lg2f(float x) {
    float y; asm("lg2.approx.f32 %0, %1;" : "=f"(y) : "f"(x)); return y;
}
// acquire load with memory clobber (no hoisting of later loads above it)
__device__ __forceinline__ int ld_acq(const int* p) {
    int v; asm volatile("ld.acquire.gpu.global.s32 %0, [%1];" : "=r"(v) : "l"(p) : "memory");
    return v;
}
__device__ __forceinline__ void st_rel(int* p, int v) {
    asm volatile("st.release.gpu.global.s32 [%0], %1;" :: "l"(p), "r"(v) : "memory");
}

constexpr float L2E  = 1.4426950408889634f;
constexpr float LN2  = 0.6931471805599453f;
constexpr float LN32 = 3.4657359027997265f;

__global__ void reset_kernel() {
    int i = threadIdx.x;
    if (i < B) { g_fw[i] = -1; g_vw[i] = 0; }
}

// grid = 128 x 256.
//  bid >= 64: WORKER block, batch b=bid-64, 8 warps.
//    Phase A: feats rows in 16-row waves (warp w does rows wave*16+{w, w+8});
//             after each wave: threadfence+syncthreads+release g_fw[b].
//    Phase B: backpointers striped t = 1+w mod 8, trailing g_vw[b].
//  bid < 64: CHAIN block, batch b=bid. 64 live threads: warp0=fwd, warp1=vit.
//    Feats read cross-SM via acquire-gated __ldcg (pipelined, L1-bypassed).
__global__ void __launch_bounds__(256, 1)
crf_pipe(const int* __restrict__ words, const int* __restrict__ lens,
         const float* __restrict__ W, const float* __restrict__ trans,
         float* __restrict__ feats, float* __restrict__ maxs,
         float* __restrict__ idxo, float* __restrict__ score)
{
    int tid  = threadIdx.x;
    int wid  = tid >> 5;
    int lane = tid & 31;

    if (blockIdx.x >= 64) {
        // ========================= WORKER BLOCK =========================
        int b = blockIdx.x - 64;
        int L = __ldg(&lens[b]);
        int w = wid;
        float w0v = __ldg(&W[0]) * 32.f;          // pad row value (idx -> 0)

        // ---- phase A: 32 waves x 16 rows ----
        for (int wave = 0; wave < T / 16; wave++) {
#pragma unroll
            for (int rnd = 0; rnd < 2; rnd++) {
                int t = wave * 16 + rnd * 8 + w;
                float s;
                if (t < L) {
                    int gw = t * B + b;
                    int wd = __ldg(&words[gw * F + lane]);
                    float s0 = 0.f, s1 = 0.f, s2 = 0.f, s3 = 0.f;
#pragma unroll
                    for (int f = 0; f < F; f += 4) {
                        int w0 = __shfl_sync(FULL, wd, f);
                        int w1 = __shfl_sync(FULL, wd, f + 1);
                        int w2 = __shfl_sync(FULL, wd, f + 2);
                        int w3 = __shfl_sync(FULL, wd, f + 3);
                        s0 += __ldg(&W[w0 + lane]); s1 += __ldg(&W[w1 + lane]);
                        s2 += __ldg(&W[w2 + lane]); s3 += __ldg(&W[w3 + lane]);
                    }
                    s = (s0 + s1) + (s2 + s3);
                } else {
                    s = w0v;
                }
                feats[(t * B + b) * K + lane] = s;
                if (t == 0) {
                    maxs[b * K + lane] = s;       // max_s[0] = feats[0]
                    idxo[b * K + lane] = 0.f;     // max_s_idx[0] = 0
                }
            }
            __threadfence();                      // all my stores -> gpu scope
            __syncthreads();                      // whole wave done
            if (tid == 0)
                st_rel(&g_fw[b], (wave == T / 16 - 1) ? T : wave * 16 + 15);
        }

        // ---- phase B: backpointers ----
        float tc[K];
#pragma unroll
        for (int j = 0; j < K; j++) tc[j] = __ldg(&trans[j * K + lane]);

        int Lc = (L < T) ? L : T;
        for (int t = 1 + w; t < Lc; t += 8) {
            while (ld_acq(&g_vw[b]) < t - 1) __nanosleep(64);
            float dp = __ldcg(&maxs[((t - 1) * B + b) * K + lane]);  // L2-coherent
            float best = __shfl_sync(FULL, dp, 0) + tc[0];
            int   bi   = 0;
#pragma unroll
            for (int j = 1; j < K; j++) {
                float sc = __shfl_sync(FULL, dp, j) + tc[j];
                if (sc > best) { best = sc; bi = j; }   // strict > : first index
            }
            idxo[(t * B + b) * K + lane] = (float)bi;
        }
        if (L < T) {
            while (ld_acq(&g_vw[b]) < L - 1) __nanosleep(64);
            float dp = __ldcg(&maxs[((L - 1) * B + b) * K + lane]);
            float best = __shfl_sync(FULL, dp, 0) + tc[0];
            int   bi   = 0;
#pragma unroll
            for (int j = 1; j < K; j++) {
                float sc = __shfl_sync(FULL, dp, j) + tc[j];
                if (sc > best) { best = sc; bi = j; }
            }
            float v = (float)bi;
            int s0i = 1 + w;
            int t0  = (L > s0i) ? s0i + ((L - s0i + 7) / 8) * 8 : s0i;
#pragma unroll 4
            for (int t = t0; t < T; t += 8)
                idxo[(t * B + b) * K + lane] = v;
        }
        return;
    }

    // ========================= CHAIN BLOCK =========================
    int b = blockIdx.x;
    if (wid >= 2) return;                     // 2 live warps only
    int L = __ldg(&lens[b]);

    auto wait_fw = [&](int need) {
        while (ld_acq(&g_fw[b]) < need) __nanosleep(32);
    };

    if (wid == 0) {
        // ---------------- forward chain (linear domain) ----------------
        float et[K];
#pragma unroll
        for (int j = 0; j < K; j++) et[j] = ex2f(__ldg(&trans[j * K + lane]) * L2E);

        wait_fw(min(18, T - 1));
        float f0 = __ldcg(&feats[b * K + lane]);
        float C0 = __shfl_sync(FULL, f0, 0);
        float E    = ex2f((f0 - C0) * L2E);
        float Ctot = C0;

        float fA = __ldcg(&feats[(1 * B + b) * K + lane]);
        float fB = __ldcg(&feats[(2 * B + b) * K + lane]);

        for (int base = 1; base < L; base += 16) {
            wait_fw(min(base + 17, T - 1));
            int end = min(base + 16, L);
            for (int t = base; t < end; t++) {
                float f = fA;
                fA = fB;
                int tp = min(t + 2, T - 1);
                fB = __ldcg(&feats[(tp * B + b) * K + lane]);   // pipelined
                float xf = ex2f(fmaf(f, L2E, -5.f));            // exp(f)/32

                float s0 = 0.f, s1 = 0.f, s2 = 0.f, s3 = 0.f;
#pragma unroll
                for (int j = 0; j < K; j += 4) {
                    s0 = fmaf(__shfl_sync(FULL, E, j),     et[j],     s0);
                    s1 = fmaf(__shfl_sync(FULL, E, j + 1), et[j + 1], s1);
                    s2 = fmaf(__shfl_sync(FULL, E, j + 2), et[j + 2], s2);
                    s3 = fmaf(__shfl_sync(FULL, E, j + 3), et[j + 3], s3);
                }
                E = ((s0 + s1) + (s2 + s3)) * xf;
                Ctot += LN32;
                if ((t & 127) == 0) {                           // renorm
                    float rr = __shfl_sync(FULL, E, 0);
                    float cc = lg2f(rr);
                    E *= ex2f(-cc);
                    Ctot += cc * LN2;
                }
            }
        }
        float e = E;
#pragma unroll
        for (int o = 16; o; o >>= 1) e += __shfl_xor_sync(FULL, e, o);
        if (lane == 0) score[b] = Ctot + lg2f(e) * LN2;

    } else {
        // ---------------- Viterbi chain ----------------
        float tc[K];
#pragma unroll
        for (int j = 0; j < K; j++) tc[j] = __ldg(&trans[j * K + lane]);

        wait_fw(min(18, T - 1));
        float delta = __ldcg(&feats[b * K + lane]);

        float fA = __ldcg(&feats[(1 * B + b) * K + lane]);
        float fB = __ldcg(&feats[(2 * B + b) * K + lane]);

        const float NEG_INF = __int_as_float(0xff800000);
        for (int base = 1; base < L; base += 16) {
            wait_fw(min(base + 17, T - 1));
            int end = min(base + 16, L);
            for (int t = base; t < end; t++) {
                float f = fA;
                fA = fB;
                int tp = min(t + 2, T - 1);
                fB = __ldcg(&feats[(tp * B + b) * K + lane]);

                float m0 = NEG_INF, m1 = NEG_INF, m2 = NEG_INF, m3 = NEG_INF;
#pragma unroll
                for (int j = 0; j < K; j += 4) {
                    m0 = fmaxf(m0, __shfl_sync(FULL, delta, j)     + tc[j]);
                    m1 = fmaxf(m1, __shfl_sync(FULL, delta, j + 1) + tc[j + 1]);
                    m2 = fmaxf(m2, __shfl_sync(FULL, delta, j + 2) + tc[j + 2]);
                    m3 = fmaxf(m3, __shfl_sync(FULL, delta, j + 3) + tc[j + 3]);
                }
                delta = fmaxf(fmaxf(m0, m1), fmaxf(m2, m3)) + f;
                maxs[(t * B + b) * K + lane] = delta;
            }
            // publish once per 16-step block
            __threadfence();
            __syncwarp();
            if (lane == 0) st_rel(&g_vw[b], end - 1);
        }
        // frozen tail: max_s[t] = delta for t in [L, T)
#pragma unroll 4
        for (int t = L; t < T; t++)
            maxs[(t * B + b) * K + lane] = delta;
        __threadfence();
        __syncwarp();
        if (lane == 0) st_rel(&g_vw[b], T);
    }
}

// ---------------------------------------------------------------------------
extern "C" void kernel_launch(void* const* d_in, const int* in_sizes, int n_in,
                              void* d_out, int out_size) {
    const int*   words = (const int*)d_in[0];     // [T,B,F] int32
    const int*   lens  = (const int*)d_in[1];     // [B] int32
    const float* W     = (const float*)d_in[2];   // [1e6] f32
    const float* trans = (const float*)d_in[3];   // [K,K] f32
    float* out   = (float*)d_out;
    float* score = out;
    float* maxs  = out + 64;
    float* idxo  = out + 64 + T * B * K;
    float* feats = out + 64 + 2 * T * B * K;

    reset_kernel<<<1, 64>>>();
    crf_pipe<<<128, 256>>>(words, lens, W, trans, feats, maxs, idxo, score);
}